// round 2
// baseline (speedup 1.0000x reference)
#include <cuda_runtime.h>
#include <cuda_bf16.h>
#include <math_constants.h>

// Problem constants
#define BB 2
#define SS 4096
#define DD 768
#define NH 6
#define NKV 2
#define REP 3
#define HD 128
#define MM (BB * SS)   // 8192

// Scratch (alloc-free rule: __device__ globals)
__device__ float g_q[MM * (NH * HD)];     // 8192 x 768  (pre-scaled)
__device__ float g_k[MM * (NKV * HD)];    // 8192 x 256
__device__ float g_v[MM * (NKV * HD)];    // 8192 x 256
__device__ float g_attn[MM * (NH * HD)];  // 8192 x 768

// ---------------------------------------------------------------------------
// C[M,N] = alpha * A[M,K] @ W[N,K]^T     (torch Linear convention)
// 128x128 tile, BK=8, 256 threads, 8x8 microtile. M%128==0, N%128==0, K%8==0.
// ---------------------------------------------------------------------------
__global__ __launch_bounds__(256, 1)
void sgemm_nt(const float* __restrict__ A, const float* __restrict__ W,
              float* __restrict__ C, int M, int N, int K, float alpha) {
    __shared__ float As[8][128];
    __shared__ float Bs[8][128];

    const int tid  = threadIdx.x;
    const int brow = blockIdx.y * 128;
    const int bcol = blockIdx.x * 128;
    const int lr   = tid >> 1;          // 0..127
    const int lc   = (tid & 1) << 2;    // 0 or 4
    const int tx   = tid & 15;
    const int ty   = tid >> 4;

    const float* Aptr = A + (size_t)(brow + lr) * K + lc;
    const float* Wptr = W + (size_t)(bcol + lr) * K + lc;

    float acc[8][8];
#pragma unroll
    for (int i = 0; i < 8; ++i)
#pragma unroll
        for (int j = 0; j < 8; ++j) acc[i][j] = 0.f;

    for (int k0 = 0; k0 < K; k0 += 8) {
        float4 a4 = *(const float4*)(Aptr + k0);
        float4 b4 = *(const float4*)(Wptr + k0);
        As[lc + 0][lr] = a4.x; As[lc + 1][lr] = a4.y;
        As[lc + 2][lr] = a4.z; As[lc + 3][lr] = a4.w;
        Bs[lc + 0][lr] = b4.x; Bs[lc + 1][lr] = b4.y;
        Bs[lc + 2][lr] = b4.z; Bs[lc + 3][lr] = b4.w;
        __syncthreads();

#pragma unroll
        for (int kk = 0; kk < 8; ++kk) {
            float a[8], b[8];
            *(float4*)(a + 0) = *(const float4*)&As[kk][ty * 8 + 0];
            *(float4*)(a + 4) = *(const float4*)&As[kk][ty * 8 + 4];
            *(float4*)(b + 0) = *(const float4*)&Bs[kk][tx * 8 + 0];
            *(float4*)(b + 4) = *(const float4*)&Bs[kk][tx * 8 + 4];
#pragma unroll
            for (int i = 0; i < 8; ++i)
#pragma unroll
                for (int j = 0; j < 8; ++j)
                    acc[i][j] = fmaf(a[i], b[j], acc[i][j]);
        }
        __syncthreads();
    }

#pragma unroll
    for (int i = 0; i < 8; ++i) {
        float* cp = C + (size_t)(brow + ty * 8 + i) * N + bcol + tx * 8;
        float4 r0, r1;
        r0.x = alpha * acc[i][0]; r0.y = alpha * acc[i][1];
        r0.z = alpha * acc[i][2]; r0.w = alpha * acc[i][3];
        r1.x = alpha * acc[i][4]; r1.y = alpha * acc[i][5];
        r1.z = alpha * acc[i][6]; r1.w = alpha * acc[i][7];
        *(float4*)(cp + 0) = r0;
        *(float4*)(cp + 4) = r1;
    }
}

// ---------------------------------------------------------------------------
// Flash attention, fp32, bidirectional (no mask), GQA.
// BQ=64 queries per CTA, BKV=64 keys per tile, 256 threads.
// grid = (S/64, B*H). Q pre-scaled by 1/sqrt(HD).
// ---------------------------------------------------------------------------
#define QK_STRIDE 68   // padded row stride for QsT/KsT ([HD][64] transposed)
#define P_STRIDE  68   // padded row stride for PsT ([64 kv][64 q])

#define ATTN_SMEM_FLOATS (HD * QK_STRIDE * 2 + 64 * HD + 64 * P_STRIDE)
#define ATTN_SMEM_BYTES  (ATTN_SMEM_FLOATS * 4)

__global__ __launch_bounds__(256, 1)
void attn_kernel(const float* __restrict__ Q, const float* __restrict__ K,
                 const float* __restrict__ V, float* __restrict__ Oout) {
    extern __shared__ float sm[];
    float* QsT = sm;                        // [HD][QK_STRIDE] : kk*68 + qrow
    float* KsT = QsT + HD * QK_STRIDE;      // [HD][QK_STRIDE] : kk*68 + krow
    float* Vs  = KsT + HD * QK_STRIDE;      // [64][HD]        : c*128 + d
    float* PsT = Vs + 64 * HD;              // [64][P_STRIDE]  : c*68 + qrow

    const int tid = threadIdx.x;
    const int tx  = tid & 15;   // 16 col groups
    const int ty  = tid >> 4;   // 16 row groups (4 q-rows each)
    const int qt  = blockIdx.x;          // 0..63
    const int hb  = blockIdx.y;          // 0..11
    const int b   = hb / NH;
    const int h   = hb % NH;
    const int g   = h / REP;

    const int qrow0 = b * SS + qt * 64;
    const int krow0 = b * SS;

    // ---- load Q tile transposed: QsT[d][r] ----
    {
        const int r  = tid >> 2;         // 0..63
        const int c4 = tid & 3;          // 0..3
        const float* qp = Q + (size_t)(qrow0 + r) * (NH * HD) + h * HD;
#pragma unroll
        for (int i = 0; i < 8; ++i) {
            int d = (c4 * 8 + i) * 4;
            float4 v = *(const float4*)(qp + d);
            QsT[(d + 0) * QK_STRIDE + r] = v.x;
            QsT[(d + 1) * QK_STRIDE + r] = v.y;
            QsT[(d + 2) * QK_STRIDE + r] = v.z;
            QsT[(d + 3) * QK_STRIDE + r] = v.w;
        }
    }

    float o[4][8];
#pragma unroll
    for (int i = 0; i < 4; ++i)
#pragma unroll
        for (int j = 0; j < 8; ++j) o[i][j] = 0.f;
    float m_i[4], l_i[4];
#pragma unroll
    for (int i = 0; i < 4; ++i) { m_i[i] = -CUDART_INF_F; l_i[i] = 0.f; }

    for (int kt = 0; kt < SS / 64; ++kt) {
        // ---- load K tile transposed + V tile direct ----
        {
            const int r  = tid >> 2;
            const int c4 = tid & 3;
            const float* kp = K + (size_t)(krow0 + kt * 64 + r) * (NKV * HD) + g * HD;
#pragma unroll
            for (int i = 0; i < 8; ++i) {
                int d = (c4 * 8 + i) * 4;
                float4 v = *(const float4*)(kp + d);
                KsT[(d + 0) * QK_STRIDE + r] = v.x;
                KsT[(d + 1) * QK_STRIDE + r] = v.y;
                KsT[(d + 2) * QK_STRIDE + r] = v.z;
                KsT[(d + 3) * QK_STRIDE + r] = v.w;
            }
            const float* vbase = V + (size_t)(krow0 + kt * 64) * (NKV * HD) + g * HD;
#pragma unroll
            for (int i = 0; i < 8; ++i) {
                int idx = tid + i * 256;          // float4 index, 0..2047
                int row = idx >> 5;
                int dc  = idx & 31;
                *(float4*)&Vs[row * HD + dc * 4] =
                    *(const float4*)(vbase + (size_t)row * (NKV * HD) + dc * 4);
            }
        }
        __syncthreads();

        // ---- S = Q @ K^T  (64x64, micro 4x4) ----
        float s[4][4];
#pragma unroll
        for (int i = 0; i < 4; ++i)
#pragma unroll
            for (int j = 0; j < 4; ++j) s[i][j] = 0.f;

#pragma unroll 8
        for (int kk = 0; kk < HD; ++kk) {
            float4 qa = *(const float4*)&QsT[kk * QK_STRIDE + ty * 4];
            float4 kb = *(const float4*)&KsT[kk * QK_STRIDE + tx * 4];
            float a[4] = {qa.x, qa.y, qa.z, qa.w};
            float bq[4] = {kb.x, kb.y, kb.z, kb.w};
#pragma unroll
            for (int i = 0; i < 4; ++i)
#pragma unroll
                for (int j = 0; j < 4; ++j)
                    s[i][j] = fmaf(a[i], bq[j], s[i][j]);
        }

        // ---- online softmax (rows = ty*4+i, reduce over 16 lanes same-ty) ----
#pragma unroll
        for (int i = 0; i < 4; ++i) {
            float mx = fmaxf(fmaxf(s[i][0], s[i][1]), fmaxf(s[i][2], s[i][3]));
            mx = fmaxf(mx, __shfl_xor_sync(0xffffffffu, mx, 8));
            mx = fmaxf(mx, __shfl_xor_sync(0xffffffffu, mx, 4));
            mx = fmaxf(mx, __shfl_xor_sync(0xffffffffu, mx, 2));
            mx = fmaxf(mx, __shfl_xor_sync(0xffffffffu, mx, 1));
            float mnew = fmaxf(m_i[i], mx);
            float corr = __expf(m_i[i] - mnew);
            m_i[i] = mnew;
            float p[4], rs = 0.f;
#pragma unroll
            for (int j = 0; j < 4; ++j) { p[j] = __expf(s[i][j] - mnew); rs += p[j]; }
            rs += __shfl_xor_sync(0xffffffffu, rs, 8);
            rs += __shfl_xor_sync(0xffffffffu, rs, 4);
            rs += __shfl_xor_sync(0xffffffffu, rs, 2);
            rs += __shfl_xor_sync(0xffffffffu, rs, 1);
            l_i[i] = l_i[i] * corr + rs;
#pragma unroll
            for (int j = 0; j < 8; ++j) o[i][j] *= corr;
#pragma unroll
            for (int j = 0; j < 4; ++j)
                PsT[(tx * 4 + j) * P_STRIDE + ty * 4 + i] = p[j];
        }
        __syncthreads();

        // ---- O += P @ V  (64x128, micro 4x8) ----
#pragma unroll 4
        for (int c = 0; c < 64; ++c) {
            float4 pa = *(const float4*)&PsT[c * P_STRIDE + ty * 4];
            float4 v0 = *(const float4*)&Vs[c * HD + tx * 8 + 0];
            float4 v1 = *(const float4*)&Vs[c * HD + tx * 8 + 4];
            float a[4]  = {pa.x, pa.y, pa.z, pa.w};
            float vv[8] = {v0.x, v0.y, v0.z, v0.w, v1.x, v1.y, v1.z, v1.w};
#pragma unroll
            for (int i = 0; i < 4; ++i)
#pragma unroll
                for (int j = 0; j < 8; ++j)
                    o[i][j] = fmaf(a[i], vv[j], o[i][j]);
        }
        __syncthreads();
    }

    // ---- epilogue ----
#pragma unroll
    for (int i = 0; i < 4; ++i) {
        float inv = 1.f / l_i[i];
        float* op = Oout + (size_t)(qrow0 + ty * 4 + i) * (NH * HD) + h * HD + tx * 8;
        float4 r0, r1;
        r0.x = o[i][0] * inv; r0.y = o[i][1] * inv;
        r0.z = o[i][2] * inv; r0.w = o[i][3] * inv;
        r1.x = o[i][4] * inv; r1.y = o[i][5] * inv;
        r1.z = o[i][6] * inv; r1.w = o[i][7] * inv;
        *(float4*)(op + 0) = r0;
        *(float4*)(op + 4) = r1;
    }
}

// ---------------------------------------------------------------------------
extern "C" void kernel_launch(void* const* d_in, const int* in_sizes, int n_in,
                              void* d_out, int out_size) {
    const float* x  = (const float*)d_in[0];
    const float* wq = (const float*)d_in[1];
    const float* wk = (const float*)d_in[2];
    const float* wv = (const float*)d_in[3];
    const float* wo = (const float*)d_in[4];
    float* out = (float*)d_out;

    float *q, *k, *v, *attn;
    cudaGetSymbolAddress((void**)&q,    g_q);
    cudaGetSymbolAddress((void**)&k,    g_k);
    cudaGetSymbolAddress((void**)&v,    g_v);
    cudaGetSymbolAddress((void**)&attn, g_attn);

    // opt-in to >48KB dynamic smem (not a stream op; graph-capture-safe)
    cudaFuncSetAttribute(attn_kernel, cudaFuncAttributeMaxDynamicSharedMemorySize,
                         ATTN_SMEM_BYTES);

    const float scale = 0.08838834764831845f;  // 1/sqrt(128)

    // projections
    sgemm_nt<<<dim3((NH * HD) / 128, MM / 128), 256>>>(x, wq, q, MM, NH * HD, DD, scale);
    sgemm_nt<<<dim3((NKV * HD) / 128, MM / 128), 256>>>(x, wk, k, MM, NKV * HD, DD, 1.f);
    sgemm_nt<<<dim3((NKV * HD) / 128, MM / 128), 256>>>(x, wv, v, MM, NKV * HD, DD, 1.f);

    // attention
    attn_kernel<<<dim3(SS / 64, BB * NH), 256, ATTN_SMEM_BYTES>>>(q, k, v, attn);

    // output projection
    sgemm_nt<<<dim3(DD / 128, MM / 128), 256>>>(attn, wo, out, MM, DD, DD, 1.f);
}

// round 3
// speedup vs baseline: 2.0261x; 2.0261x over previous
#include <cuda_runtime.h>
#include <cuda_bf16.h>
#include <math_constants.h>
#include <cstdint>

// Problem constants
#define BB 2
#define SS 4096
#define DD 768
#define NH 6
#define NKV 2
#define REP 3
#define HD 128
#define MM (BB * SS)   // 8192

// Scratch (alloc-free rule: __device__ globals)
__device__ float g_q[MM * (NH * HD)];     // pre-scaled by 1/sqrt(HD)
__device__ float g_k[MM * (NKV * HD)];
__device__ float g_v[MM * (NKV * HD)];
__device__ float g_attn[MM * (NH * HD)];

// ---------------------------------------------------------------------------
__device__ __forceinline__ float tf32f(float x) {
    uint32_t u;
    asm("cvt.rna.tf32.f32 %0, %1;" : "=r"(u) : "f"(x));
    return __uint_as_float(u);
}
__device__ __forceinline__ uint32_t fbits(float x) { return __float_as_uint(x); }

#define MMA_TF32(c, a0, a1, a2, a3, b0, b1)                                          \
    asm volatile(                                                                    \
        "mma.sync.aligned.m16n8k8.row.col.f32.tf32.tf32.f32 "                        \
        "{%0,%1,%2,%3}, {%4,%5,%6,%7}, {%8,%9}, {%0,%1,%2,%3};"                      \
        : "+f"(c[0]), "+f"(c[1]), "+f"(c[2]), "+f"(c[3])                             \
        : "r"(a0), "r"(a1), "r"(a2), "r"(a3), "r"(b0), "r"(b1))

// ---------------------------------------------------------------------------
// C[M,N] = alpha * A[M,K] @ W[N,K]^T   via tf32 mma.sync.
// CTA tile 128x128, K-chunk 32, 256 threads (8 warps: 2m x 4n, warp 64x32).
// SPLIT=1: 3xtf32 error-compensated (hi/lo) for ~fp32 accuracy.
// ---------------------------------------------------------------------------
#define GS 36   // padded smem stride (floats)

template <int SPLIT>
__global__ __launch_bounds__(256, 1)
void gemm_tf32(const float* __restrict__ A, const float* __restrict__ W,
               float* __restrict__ C, int M, int N, int K, float alpha) {
    extern __shared__ float sm[];
    float* Ah = sm;                    // [128][GS]
    float* Bh = Ah + 128 * GS;
    float* Al = SPLIT ? Bh + 128 * GS : Ah;
    float* Bl = SPLIT ? Al + 128 * GS : Bh;

    const int tid  = threadIdx.x;
    const int lane = tid & 31;
    const int wid  = tid >> 5;
    const int wm   = wid & 1;    // 0..1 -> 64 rows
    const int wn   = wid >> 1;   // 0..3 -> 32 cols
    const int g    = lane >> 2;
    const int t    = lane & 3;

    const int brow = blockIdx.y * 128;
    const int bcol = blockIdx.x * 128;

    const int lrow = tid >> 1;
    const int half = tid & 1;
    const float* Ap = A + (size_t)(brow + lrow) * K + half * 16;
    const float* Wp = W + (size_t)(bcol + lrow) * K + half * 16;

    float acc[4][4][4];
#pragma unroll
    for (int i = 0; i < 4; ++i)
#pragma unroll
        for (int j = 0; j < 4; ++j)
#pragma unroll
            for (int c = 0; c < 4; ++c) acc[i][j][c] = 0.f;

    for (int k0 = 0; k0 < K; k0 += 32) {
        float4 av[4], bv[4];
#pragma unroll
        for (int i = 0; i < 4; ++i) {
            av[i] = *(const float4*)(Ap + k0 + i * 4);
            bv[i] = *(const float4*)(Wp + k0 + i * 4);
        }
        __syncthreads();   // prev chunk's frag reads complete
#pragma unroll
        for (int i = 0; i < 4; ++i) {
            const float* afp = (const float*)&av[i];
            const float* bfp = (const float*)&bv[i];
#pragma unroll
            for (int j = 0; j < 4; ++j) {
                int col = half * 16 + i * 4 + j;
                float a = afp[j], b = bfp[j];
                float ah = tf32f(a), bh = tf32f(b);
                Ah[lrow * GS + col] = ah;
                Bh[lrow * GS + col] = bh;
                if (SPLIT) {
                    Al[lrow * GS + col] = tf32f(a - ah);
                    Bl[lrow * GS + col] = tf32f(b - bh);
                }
            }
        }
        __syncthreads();

#pragma unroll
        for (int ks = 0; ks < 4; ++ks) {
            uint32_t af[4][4], bf[4][2];
            uint32_t afl[4][4], bfl[4][2];
#pragma unroll
            for (int mf = 0; mf < 4; ++mf) {
                int row = wm * 64 + mf * 16 + g;
                af[mf][0] = fbits(Ah[row * GS + ks * 8 + t]);
                af[mf][1] = fbits(Ah[(row + 8) * GS + ks * 8 + t]);
                af[mf][2] = fbits(Ah[row * GS + ks * 8 + t + 4]);
                af[mf][3] = fbits(Ah[(row + 8) * GS + ks * 8 + t + 4]);
                if (SPLIT) {
                    afl[mf][0] = fbits(Al[row * GS + ks * 8 + t]);
                    afl[mf][1] = fbits(Al[(row + 8) * GS + ks * 8 + t]);
                    afl[mf][2] = fbits(Al[row * GS + ks * 8 + t + 4]);
                    afl[mf][3] = fbits(Al[(row + 8) * GS + ks * 8 + t + 4]);
                }
            }
#pragma unroll
            for (int nf = 0; nf < 4; ++nf) {
                int coln = wn * 32 + nf * 8 + g;
                bf[nf][0] = fbits(Bh[coln * GS + ks * 8 + t]);
                bf[nf][1] = fbits(Bh[coln * GS + ks * 8 + t + 4]);
                if (SPLIT) {
                    bfl[nf][0] = fbits(Bl[coln * GS + ks * 8 + t]);
                    bfl[nf][1] = fbits(Bl[coln * GS + ks * 8 + t + 4]);
                }
            }
#pragma unroll
            for (int mf = 0; mf < 4; ++mf)
#pragma unroll
                for (int nf = 0; nf < 4; ++nf) {
                    MMA_TF32(acc[mf][nf], af[mf][0], af[mf][1], af[mf][2], af[mf][3],
                             bf[nf][0], bf[nf][1]);
                    if (SPLIT) {
                        MMA_TF32(acc[mf][nf], af[mf][0], af[mf][1], af[mf][2], af[mf][3],
                                 bfl[nf][0], bfl[nf][1]);
                        MMA_TF32(acc[mf][nf], afl[mf][0], afl[mf][1], afl[mf][2], afl[mf][3],
                                 bf[nf][0], bf[nf][1]);
                    }
                }
        }
    }

#pragma unroll
    for (int mf = 0; mf < 4; ++mf)
#pragma unroll
        for (int nf = 0; nf < 4; ++nf) {
            int row = brow + wm * 64 + mf * 16 + g;
            int col = bcol + wn * 32 + nf * 8 + 2 * t;
            float2 v0 = {alpha * acc[mf][nf][0], alpha * acc[mf][nf][1]};
            float2 v1 = {alpha * acc[mf][nf][2], alpha * acc[mf][nf][3]};
            *(float2*)(C + (size_t)row * N + col) = v0;
            *(float2*)(C + (size_t)(row + 8) * N + col) = v1;
        }
}

// ---------------------------------------------------------------------------
// Flash attention, tf32 tensor cores. BQ=BKV=64, HD=128, 256 threads.
// Warps: 4(q-rows,16 each) x 2(k-cols,32 each); PV: same q split, 2x 64 d-cols.
// ---------------------------------------------------------------------------
#define AQS 132
#define AKS 132
#define AVS 136
#define APS 68

#define ATTN_SMEM_FLOATS (64 * AQS + 64 * AKS + 64 * AVS + 64 * APS + 256)
#define ATTN_SMEM_BYTES  (ATTN_SMEM_FLOATS * 4)

__global__ __launch_bounds__(256, 1)
void attn_tc(const float* __restrict__ Q, const float* __restrict__ K,
             const float* __restrict__ V, float* __restrict__ Oout) {
    extern __shared__ float sm[];
    float* Qs = sm;                  // [64][AQS]
    float* Ks = Qs + 64 * AQS;       // [64][AKS]
    float* Vs = Ks + 64 * AKS;       // [64][AVS]
    float* Ps = Vs + 64 * AVS;       // [64][APS]
    float* redmax = Ps + 64 * APS;   // [2][64]
    float* redsum = redmax + 128;    // [2][64]

    const int tid  = threadIdx.x;
    const int lane = tid & 31;
    const int wid  = tid >> 5;
    const int wq4  = wid & 3;    // q-row group (16 rows)
    const int wk2  = wid >> 2;   // k-col / d-col half
    const int g    = lane >> 2;
    const int t    = lane & 3;
    const int row0 = wq4 * 16 + g;   // +8 for second row

    const int qt = blockIdx.x;
    const int hb = blockIdx.y;
    const int b  = hb / NH;
    const int h  = hb % NH;
    const int hg = h / REP;

    const int qrow0 = b * SS + qt * 64;
    const int krow0 = b * SS;

    // ---- load Q tile (pre-scaled), tf32-round at store ----
    {
        const int r  = tid >> 2;
        const int q4 = tid & 3;
        const float* qp = Q + (size_t)(qrow0 + r) * (NH * HD) + h * HD;
#pragma unroll
        for (int i = 0; i < 8; ++i) {
            int k4 = q4 * 8 + i;
            float4 v = *(const float4*)(qp + k4 * 4);
            Qs[r * AQS + k4 * 4 + 0] = tf32f(v.x);
            Qs[r * AQS + k4 * 4 + 1] = tf32f(v.y);
            Qs[r * AQS + k4 * 4 + 2] = tf32f(v.z);
            Qs[r * AQS + k4 * 4 + 3] = tf32f(v.w);
        }
    }
    __syncthreads();

    // ---- hoist Q fragments (persistent across kt) ----
    uint32_t qf[16][4];
#pragma unroll
    for (int ks = 0; ks < 16; ++ks) {
        qf[ks][0] = fbits(Qs[row0 * AQS + ks * 8 + t]);
        qf[ks][1] = fbits(Qs[(row0 + 8) * AQS + ks * 8 + t]);
        qf[ks][2] = fbits(Qs[row0 * AQS + ks * 8 + t + 4]);
        qf[ks][3] = fbits(Qs[(row0 + 8) * AQS + ks * 8 + t + 4]);
    }

    float o[8][4];
#pragma unroll
    for (int nf = 0; nf < 8; ++nf)
#pragma unroll
        for (int c = 0; c < 4; ++c) o[nf][c] = 0.f;
    float m0 = -CUDART_INF_F, m1 = -CUDART_INF_F, l0 = 0.f, l1 = 0.f;

    for (int kt = 0; kt < SS / 64; ++kt) {
        __syncthreads();   // prev iter's PV reads done
        // ---- load K,V tiles, tf32-round ----
        {
            const int r  = tid >> 2;
            const int q4 = tid & 3;
            const float* kp = K + (size_t)(krow0 + kt * 64 + r) * (NKV * HD) + hg * HD;
            const float* vp = V + (size_t)(krow0 + kt * 64 + r) * (NKV * HD) + hg * HD;
#pragma unroll
            for (int i = 0; i < 8; ++i) {
                int k4 = q4 * 8 + i;
                float4 kv = *(const float4*)(kp + k4 * 4);
                Ks[r * AKS + k4 * 4 + 0] = tf32f(kv.x);
                Ks[r * AKS + k4 * 4 + 1] = tf32f(kv.y);
                Ks[r * AKS + k4 * 4 + 2] = tf32f(kv.z);
                Ks[r * AKS + k4 * 4 + 3] = tf32f(kv.w);
                float4 vv = *(const float4*)(vp + k4 * 4);
                Vs[r * AVS + k4 * 4 + 0] = tf32f(vv.x);
                Vs[r * AVS + k4 * 4 + 1] = tf32f(vv.y);
                Vs[r * AVS + k4 * 4 + 2] = tf32f(vv.z);
                Vs[r * AVS + k4 * 4 + 3] = tf32f(vv.w);
            }
        }
        __syncthreads();

        // ---- S = Q @ K^T : warp computes 16(q) x 32(k) ----
        float s[4][4];
#pragma unroll
        for (int nf = 0; nf < 4; ++nf)
#pragma unroll
            for (int c = 0; c < 4; ++c) s[nf][c] = 0.f;

#pragma unroll
        for (int ks = 0; ks < 16; ++ks) {
#pragma unroll
            for (int nf = 0; nf < 4; ++nf) {
                int coln = wk2 * 32 + nf * 8 + g;
                uint32_t b0 = fbits(Ks[coln * AKS + ks * 8 + t]);
                uint32_t b1 = fbits(Ks[coln * AKS + ks * 8 + t + 4]);
                MMA_TF32(s[nf], qf[ks][0], qf[ks][1], qf[ks][2], qf[ks][3], b0, b1);
            }
        }

        // ---- online softmax (rows row0, row0+8), cross-warp via smem ----
        float mx0 = -CUDART_INF_F, mx1 = -CUDART_INF_F;
#pragma unroll
        for (int nf = 0; nf < 4; ++nf) {
            mx0 = fmaxf(mx0, fmaxf(s[nf][0], s[nf][1]));
            mx1 = fmaxf(mx1, fmaxf(s[nf][2], s[nf][3]));
        }
        mx0 = fmaxf(mx0, __shfl_xor_sync(0xffffffffu, mx0, 1));
        mx0 = fmaxf(mx0, __shfl_xor_sync(0xffffffffu, mx0, 2));
        mx1 = fmaxf(mx1, __shfl_xor_sync(0xffffffffu, mx1, 1));
        mx1 = fmaxf(mx1, __shfl_xor_sync(0xffffffffu, mx1, 2));
        if (t == 0) {
            redmax[wk2 * 64 + row0]     = mx0;
            redmax[wk2 * 64 + row0 + 8] = mx1;
        }
        __syncthreads();
        float tm0 = fmaxf(redmax[row0], redmax[64 + row0]);
        float tm1 = fmaxf(redmax[row0 + 8], redmax[64 + row0 + 8]);
        float mn0 = fmaxf(m0, tm0), mn1 = fmaxf(m1, tm1);
        float corr0 = __expf(m0 - mn0), corr1 = __expf(m1 - mn1);
        m0 = mn0; m1 = mn1;

        float sum0 = 0.f, sum1 = 0.f;
#pragma unroll
        for (int nf = 0; nf < 4; ++nf) {
            float p00 = __expf(s[nf][0] - mn0);
            float p01 = __expf(s[nf][1] - mn0);
            float p10 = __expf(s[nf][2] - mn1);
            float p11 = __expf(s[nf][3] - mn1);
            sum0 += p00 + p01;
            sum1 += p10 + p11;
            int col = wk2 * 32 + nf * 8 + 2 * t;
            Ps[row0 * APS + col]           = tf32f(p00);
            Ps[row0 * APS + col + 1]       = tf32f(p01);
            Ps[(row0 + 8) * APS + col]     = tf32f(p10);
            Ps[(row0 + 8) * APS + col + 1] = tf32f(p11);
        }
        sum0 += __shfl_xor_sync(0xffffffffu, sum0, 1);
        sum0 += __shfl_xor_sync(0xffffffffu, sum0, 2);
        sum1 += __shfl_xor_sync(0xffffffffu, sum1, 1);
        sum1 += __shfl_xor_sync(0xffffffffu, sum1, 2);
        if (t == 0) {
            redsum[wk2 * 64 + row0]     = sum0;
            redsum[wk2 * 64 + row0 + 8] = sum1;
        }
        __syncthreads();
        float rs0 = redsum[row0] + redsum[64 + row0];
        float rs1 = redsum[row0 + 8] + redsum[64 + row0 + 8];
        l0 = l0 * corr0 + rs0;
        l1 = l1 * corr1 + rs1;
#pragma unroll
        for (int nf = 0; nf < 8; ++nf) {
            o[nf][0] *= corr0; o[nf][1] *= corr0;
            o[nf][2] *= corr1; o[nf][3] *= corr1;
        }

        // ---- O += P @ V : warp computes 16(q) x 64(d), d-half = wk2 ----
#pragma unroll
        for (int ks = 0; ks < 8; ++ks) {
            uint32_t a0 = fbits(Ps[row0 * APS + ks * 8 + t]);
            uint32_t a1 = fbits(Ps[(row0 + 8) * APS + ks * 8 + t]);
            uint32_t a2 = fbits(Ps[row0 * APS + ks * 8 + t + 4]);
            uint32_t a3 = fbits(Ps[(row0 + 8) * APS + ks * 8 + t + 4]);
#pragma unroll
            for (int nf = 0; nf < 8; ++nf) {
                int d = wk2 * 64 + nf * 8 + g;
                uint32_t b0 = fbits(Vs[(ks * 8 + t) * AVS + d]);
                uint32_t b1 = fbits(Vs[(ks * 8 + t + 4) * AVS + d]);
                MMA_TF32(o[nf], a0, a1, a2, a3, b0, b1);
            }
        }
    }

    // ---- epilogue ----
    float inv0 = 1.f / l0, inv1 = 1.f / l1;
#pragma unroll
    for (int nf = 0; nf < 8; ++nf) {
        int col = wk2 * 64 + nf * 8 + 2 * t;
        float* op0 = Oout + (size_t)(qrow0 + row0) * (NH * HD) + h * HD + col;
        float* op1 = Oout + (size_t)(qrow0 + row0 + 8) * (NH * HD) + h * HD + col;
        float2 v0 = {o[nf][0] * inv0, o[nf][1] * inv0};
        float2 v1 = {o[nf][2] * inv1, o[nf][3] * inv1};
        *(float2*)op0 = v0;
        *(float2*)op1 = v1;
    }
}

// ---------------------------------------------------------------------------
extern "C" void kernel_launch(void* const* d_in, const int* in_sizes, int n_in,
                              void* d_out, int out_size) {
    const float* x  = (const float*)d_in[0];
    const float* wq = (const float*)d_in[1];
    const float* wk = (const float*)d_in[2];
    const float* wv = (const float*)d_in[3];
    const float* wo = (const float*)d_in[4];
    float* out = (float*)d_out;

    float *q, *k, *v, *attn;
    cudaGetSymbolAddress((void**)&q,    g_q);
    cudaGetSymbolAddress((void**)&k,    g_k);
    cudaGetSymbolAddress((void**)&v,    g_v);
    cudaGetSymbolAddress((void**)&attn, g_attn);

    const int smem_g0 = 2 * 128 * GS * 4;   // 36 KB
    const int smem_g1 = 4 * 128 * GS * 4;   // 72 KB
    cudaFuncSetAttribute(gemm_tf32<0>, cudaFuncAttributeMaxDynamicSharedMemorySize, smem_g0);
    cudaFuncSetAttribute(gemm_tf32<1>, cudaFuncAttributeMaxDynamicSharedMemorySize, smem_g1);
    cudaFuncSetAttribute(attn_tc, cudaFuncAttributeMaxDynamicSharedMemorySize, ATTN_SMEM_BYTES);

    const float scale = 0.08838834764831845f;  // 1/sqrt(128)

    // projections (tf32)
    gemm_tf32<0><<<dim3((NH * HD) / 128, MM / 128), 256, smem_g0>>>(x, wq, q, MM, NH * HD, DD, scale);
    gemm_tf32<0><<<dim3((NKV * HD) / 128, MM / 128), 256, smem_g0>>>(x, wk, k, MM, NKV * HD, DD, 1.f);
    gemm_tf32<0><<<dim3((NKV * HD) / 128, MM / 128), 256, smem_g0>>>(x, wv, v, MM, NKV * HD, DD, 1.f);

    // attention (tf32 tensor cores)
    attn_tc<<<dim3(SS / 64, BB * NH), 256, ATTN_SMEM_BYTES>>>(q, k, v, attn);

    // output projection (3xtf32 compensated)
    gemm_tf32<1><<<dim3(DD / 128, MM / 128), 256, smem_g1>>>(attn, wo, out, MM, DD, DD, 1.f);
}

// round 4
// speedup vs baseline: 2.2348x; 1.1030x over previous
#include <cuda_runtime.h>
#include <cuda_bf16.h>
#include <math_constants.h>
#include <cstdint>

// Problem constants
#define BB 2
#define SS 4096
#define DD 768
#define NH 6
#define NKV 2
#define REP 3
#define HD 128
#define MM (BB * SS)   // 8192

// Scratch (alloc-free rule: __device__ globals)
__device__ float g_q[MM * (NH * HD)];     // pre-scaled by 1/sqrt(HD)
__device__ float g_k[MM * (NKV * HD)];
__device__ float g_v[MM * (NKV * HD)];
__device__ float g_attn[MM * (NH * HD)];

// ---------------------------------------------------------------------------
__device__ __forceinline__ float tf32f(float x) {
    uint32_t u;
    asm("cvt.rna.tf32.f32 %0, %1;" : "=r"(u) : "f"(x));
    return __uint_as_float(u);
}
__device__ __forceinline__ uint32_t fbits(float x) { return __float_as_uint(x); }

#define MMA_TF32(c, a0, a1, a2, a3, b0, b1)                                          \
    asm volatile(                                                                    \
        "mma.sync.aligned.m16n8k8.row.col.f32.tf32.tf32.f32 "                        \
        "{%0,%1,%2,%3}, {%4,%5,%6,%7}, {%8,%9}, {%0,%1,%2,%3};"                      \
        : "+f"(c[0]), "+f"(c[1]), "+f"(c[2]), "+f"(c[3])                             \
        : "r"(a0), "r"(a1), "r"(a2), "r"(a3), "r"(b0), "r"(b1))

// ---------------------------------------------------------------------------
// C[M,N] = alpha * A[M,K] @ W[N,K]^T   via tf32 mma.sync.  (unchanged R3)
// ---------------------------------------------------------------------------
#define GS 36

template <int SPLIT>
__global__ __launch_bounds__(256, 1)
void gemm_tf32(const float* __restrict__ A, const float* __restrict__ W,
               float* __restrict__ C, int M, int N, int K, float alpha) {
    extern __shared__ float sm[];
    float* Ah = sm;
    float* Bh = Ah + 128 * GS;
    float* Al = SPLIT ? Bh + 128 * GS : Ah;
    float* Bl = SPLIT ? Al + 128 * GS : Bh;

    const int tid  = threadIdx.x;
    const int lane = tid & 31;
    const int wid  = tid >> 5;
    const int wm   = wid & 1;
    const int wn   = wid >> 1;
    const int g    = lane >> 2;
    const int t    = lane & 3;

    const int brow = blockIdx.y * 128;
    const int bcol = blockIdx.x * 128;

    const int lrow = tid >> 1;
    const int half = tid & 1;
    const float* Ap = A + (size_t)(brow + lrow) * K + half * 16;
    const float* Wp = W + (size_t)(bcol + lrow) * K + half * 16;

    float acc[4][4][4];
#pragma unroll
    for (int i = 0; i < 4; ++i)
#pragma unroll
        for (int j = 0; j < 4; ++j)
#pragma unroll
            for (int c = 0; c < 4; ++c) acc[i][j][c] = 0.f;

    for (int k0 = 0; k0 < K; k0 += 32) {
        float4 av[4], bv[4];
#pragma unroll
        for (int i = 0; i < 4; ++i) {
            av[i] = *(const float4*)(Ap + k0 + i * 4);
            bv[i] = *(const float4*)(Wp + k0 + i * 4);
        }
        __syncthreads();
#pragma unroll
        for (int i = 0; i < 4; ++i) {
            const float* afp = (const float*)&av[i];
            const float* bfp = (const float*)&bv[i];
#pragma unroll
            for (int j = 0; j < 4; ++j) {
                int col = half * 16 + i * 4 + j;
                float a = afp[j], b = bfp[j];
                float ah = tf32f(a), bh = tf32f(b);
                Ah[lrow * GS + col] = ah;
                Bh[lrow * GS + col] = bh;
                if (SPLIT) {
                    Al[lrow * GS + col] = tf32f(a - ah);
                    Bl[lrow * GS + col] = tf32f(b - bh);
                }
            }
        }
        __syncthreads();

#pragma unroll
        for (int ks = 0; ks < 4; ++ks) {
            uint32_t af[4][4], bf[4][2];
            uint32_t afl[4][4], bfl[4][2];
#pragma unroll
            for (int mf = 0; mf < 4; ++mf) {
                int row = wm * 64 + mf * 16 + g;
                af[mf][0] = fbits(Ah[row * GS + ks * 8 + t]);
                af[mf][1] = fbits(Ah[(row + 8) * GS + ks * 8 + t]);
                af[mf][2] = fbits(Ah[row * GS + ks * 8 + t + 4]);
                af[mf][3] = fbits(Ah[(row + 8) * GS + ks * 8 + t + 4]);
                if (SPLIT) {
                    afl[mf][0] = fbits(Al[row * GS + ks * 8 + t]);
                    afl[mf][1] = fbits(Al[(row + 8) * GS + ks * 8 + t]);
                    afl[mf][2] = fbits(Al[row * GS + ks * 8 + t + 4]);
                    afl[mf][3] = fbits(Al[(row + 8) * GS + ks * 8 + t + 4]);
                }
            }
#pragma unroll
            for (int nf = 0; nf < 4; ++nf) {
                int coln = wn * 32 + nf * 8 + g;
                bf[nf][0] = fbits(Bh[coln * GS + ks * 8 + t]);
                bf[nf][1] = fbits(Bh[coln * GS + ks * 8 + t + 4]);
                if (SPLIT) {
                    bfl[nf][0] = fbits(Bl[coln * GS + ks * 8 + t]);
                    bfl[nf][1] = fbits(Bl[coln * GS + ks * 8 + t + 4]);
                }
            }
#pragma unroll
            for (int mf = 0; mf < 4; ++mf)
#pragma unroll
                for (int nf = 0; nf < 4; ++nf) {
                    MMA_TF32(acc[mf][nf], af[mf][0], af[mf][1], af[mf][2], af[mf][3],
                             bf[nf][0], bf[nf][1]);
                    if (SPLIT) {
                        MMA_TF32(acc[mf][nf], af[mf][0], af[mf][1], af[mf][2], af[mf][3],
                                 bfl[nf][0], bfl[nf][1]);
                        MMA_TF32(acc[mf][nf], afl[mf][0], afl[mf][1], afl[mf][2], afl[mf][3],
                                 bf[nf][0], bf[nf][1]);
                    }
                }
        }
    }

#pragma unroll
    for (int mf = 0; mf < 4; ++mf)
#pragma unroll
        for (int nf = 0; nf < 4; ++nf) {
            int row = brow + wm * 64 + mf * 16 + g;
            int col = bcol + wn * 32 + nf * 8 + 2 * t;
            float2 v0 = {alpha * acc[mf][nf][0], alpha * acc[mf][nf][1]};
            float2 v1 = {alpha * acc[mf][nf][2], alpha * acc[mf][nf][3]};
            *(float2*)(C + (size_t)row * N + col) = v0;
            *(float2*)(C + (size_t)(row + 8) * N + col) = v1;
        }
}

// ---------------------------------------------------------------------------
// Flash attention v2: paired-float2 smem, warp-private softmax, split-k merge.
// BQ=BKV=64, 256 thr. Warp (wq4, wk2): 16 q-rows, own 32 kv-cols, all 128 d.
// ---------------------------------------------------------------------------
#define SK2 258          // Ks2 stride (float2) per ks-chunk
#define SV2 513          // Vs2 stride per (half,ks)
#define SP2 257          // Ps2 stride per (half,ks)
#define KS2_OFF 0
#define VS2_OFF (16 * SK2)                 // 4128
#define PS2_OFF (VS2_OFF + 8 * SV2)        // 8232
#define ML_OFF  (PS2_OFF + 8 * SP2)        // 10288 (float2 units)
#define ATTN2_SMEM_BYTES ((ML_OFF + 128) * 8)   // 83328

__global__ __launch_bounds__(256, 1)
void attn_tc2(const float* __restrict__ Q, const float* __restrict__ K,
              const float* __restrict__ V, float* __restrict__ Oout) {
    extern __shared__ float2 smf2[];
    float2* Ks2 = smf2 + KS2_OFF;
    float2* Vs2 = smf2 + VS2_OFF;
    float2* Ps2 = smf2 + PS2_OFF;
    float*  mlb = (float*)(smf2 + ML_OFF);   // [2][2][64]: m then l
    float*  Qs  = (float*)smf2;              // overlay (pre-loop), [64][132]
    float2* stg = smf2;                      // overlay (epilogue), [64][68]

    const int tid  = threadIdx.x;
    const int lane = tid & 31;
    const int wid  = tid >> 5;
    const int wq4  = wid & 3;
    const int wk2  = wid >> 2;
    const int g    = lane >> 2;
    const int t    = lane & 3;
    const int row0 = wq4 * 16 + g;
    const int row1 = row0 + 8;

    const int qt = blockIdx.x;
    const int hb = blockIdx.y;
    const int b  = hb / NH;
    const int h  = hb % NH;
    const int hg = h / REP;

    const int qrow0 = b * SS + qt * 64;
    const int krow0 = b * SS;

    // ---- load Q (pre-scaled) into Qs, tf32 rounded ----
    {
        const int r  = tid >> 2;
        const int c4 = tid & 3;
        const float* qp = Q + (size_t)(qrow0 + r) * (NH * HD) + h * HD;
#pragma unroll
        for (int i = 0; i < 8; ++i) {
            int k4 = c4 * 8 + i;
            float4 v = *(const float4*)(qp + k4 * 4);
            Qs[r * 132 + k4 * 4 + 0] = tf32f(v.x);
            Qs[r * 132 + k4 * 4 + 1] = tf32f(v.y);
            Qs[r * 132 + k4 * 4 + 2] = tf32f(v.z);
            Qs[r * 132 + k4 * 4 + 3] = tf32f(v.w);
        }
    }
    __syncthreads();

    // ---- hoist Q fragments ----
    uint32_t qf[16][4];
#pragma unroll
    for (int ks = 0; ks < 16; ++ks) {
        qf[ks][0] = fbits(Qs[row0 * 132 + ks * 8 + t]);
        qf[ks][1] = fbits(Qs[row1 * 132 + ks * 8 + t]);
        qf[ks][2] = fbits(Qs[row0 * 132 + ks * 8 + t + 4]);
        qf[ks][3] = fbits(Qs[row1 * 132 + ks * 8 + t + 4]);
    }

    float o[16][4];
#pragma unroll
    for (int nf = 0; nf < 16; ++nf)
#pragma unroll
        for (int c = 0; c < 4; ++c) o[nf][c] = 0.f;
    float m0 = -CUDART_INF_F, m1 = -CUDART_INF_F, l0 = 0.f, l1 = 0.f;

#pragma unroll 1
    for (int kt = 0; kt < SS / 64; ++kt) {
        __syncthreads();   // Qs hoist done / prev iter smem reads done

        // ---- K loader: pairs {K[r][ks*8+t'], K[r][ks*8+t'+4]} ----
        {
            const int r  = tid >> 2;
            const int c4 = tid & 3;
            const float* kp = K + (size_t)(krow0 + kt * 64 + r) * (NKV * HD) + hg * HD;
#pragma unroll
            for (int i = 0; i < 4; ++i) {
                int ks = c4 * 4 + i;
                float4 e0 = *(const float4*)(kp + ks * 8);
                float4 e1 = *(const float4*)(kp + ks * 8 + 4);
                float2* dst = Ks2 + ks * SK2 + r * 4;
                dst[0] = make_float2(tf32f(e0.x), tf32f(e1.x));
                dst[1] = make_float2(tf32f(e0.y), tf32f(e1.y));
                dst[2] = make_float2(tf32f(e0.z), tf32f(e1.z));
                dst[3] = make_float2(tf32f(e0.w), tf32f(e1.w));
            }
        }
        // ---- V loader: pairs {V[r][d], V[r+4][d]} ----
        {
            const int p  = tid >> 3;           // pair-row 0..31
            const int db = (tid & 7) * 16;
            const int half = p >> 4;
            const int ksv  = (p >> 2) & 3;
            const int tt   = p & 3;
            const int r0 = half * 32 + ksv * 8 + tt;
            const float* v0p = V + (size_t)(krow0 + kt * 64 + r0) * (NKV * HD) + hg * HD;
            const float* v1p = v0p + 4 * (NKV * HD);
            float2* vb = Vs2 + (half * 4 + ksv) * SV2 + tt;
#pragma unroll
            for (int j = 0; j < 4; ++j) {
                int d0 = db + j * 4;
                float4 a = *(const float4*)(v0p + d0);
                float4 c = *(const float4*)(v1p + d0);
                vb[(d0 + 0) * 4] = make_float2(tf32f(a.x), tf32f(c.x));
                vb[(d0 + 1) * 4] = make_float2(tf32f(a.y), tf32f(c.y));
                vb[(d0 + 2) * 4] = make_float2(tf32f(a.z), tf32f(c.z));
                vb[(d0 + 3) * 4] = make_float2(tf32f(a.w), tf32f(c.w));
            }
        }
        __syncthreads();

        // ---- S = Q @ K^T : 16q x 32k (warp's own kv half) ----
        float s[4][4];
#pragma unroll
        for (int nf = 0; nf < 4; ++nf)
#pragma unroll
            for (int c = 0; c < 4; ++c) s[nf][c] = 0.f;

#pragma unroll
        for (int ks = 0; ks < 16; ++ks) {
#pragma unroll
            for (int nf = 0; nf < 4; ++nf) {
                float2 kb = Ks2[ks * SK2 + (wk2 * 32 + nf * 8 + g) * 4 + t];
                MMA_TF32(s[nf], qf[ks][0], qf[ks][1], qf[ks][2], qf[ks][3],
                         fbits(kb.x), fbits(kb.y));
            }
        }

        // ---- warp-local online softmax ----
        float mx0 = -CUDART_INF_F, mx1 = -CUDART_INF_F;
#pragma unroll
        for (int nf = 0; nf < 4; ++nf) {
            mx0 = fmaxf(mx0, fmaxf(s[nf][0], s[nf][1]));
            mx1 = fmaxf(mx1, fmaxf(s[nf][2], s[nf][3]));
        }
        mx0 = fmaxf(mx0, __shfl_xor_sync(0xffffffffu, mx0, 1));
        mx0 = fmaxf(mx0, __shfl_xor_sync(0xffffffffu, mx0, 2));
        mx1 = fmaxf(mx1, __shfl_xor_sync(0xffffffffu, mx1, 1));
        mx1 = fmaxf(mx1, __shfl_xor_sync(0xffffffffu, mx1, 2));
        float mn0 = fmaxf(m0, mx0), mn1 = fmaxf(m1, mx1);
        float corr0 = __expf(m0 - mn0), corr1 = __expf(m1 - mn1);
        m0 = mn0; m1 = mn1;
        if (!__all_sync(0xffffffffu, (corr0 == 1.f) && (corr1 == 1.f))) {
#pragma unroll
            for (int nf = 0; nf < 16; ++nf) {
                o[nf][0] *= corr0; o[nf][1] *= corr0;
                o[nf][2] *= corr1; o[nf][3] *= corr1;
            }
        }

        float sum0 = 0.f, sum1 = 0.f;
        {
            float* pbase = (float*)Ps2;
            const int lc0 = 2 * t, lc1 = 2 * t + 1;
            const int o00 = (lc0 & 3) * 2 + (lc0 >> 2);
            const int o01 = (lc1 & 3) * 2 + (lc1 >> 2);
#pragma unroll
            for (int nf = 0; nf < 4; ++nf) {
                float p00 = __expf(s[nf][0] - mn0);
                float p01 = __expf(s[nf][1] - mn0);
                float p10 = __expf(s[nf][2] - mn1);
                float p11 = __expf(s[nf][3] - mn1);
                sum0 += p00 + p01;
                sum1 += p10 + p11;
                int bf = (wk2 * 4 + nf) * SP2 * 2;
                pbase[bf + row0 * 8 + o00] = tf32f(p00);
                pbase[bf + row0 * 8 + o01] = tf32f(p01);
                pbase[bf + row1 * 8 + o00] = tf32f(p10);
                pbase[bf + row1 * 8 + o01] = tf32f(p11);
            }
        }
        sum0 += __shfl_xor_sync(0xffffffffu, sum0, 1);
        sum0 += __shfl_xor_sync(0xffffffffu, sum0, 2);
        sum1 += __shfl_xor_sync(0xffffffffu, sum1, 1);
        sum1 += __shfl_xor_sync(0xffffffffu, sum1, 2);
        l0 = l0 * corr0 + sum0;
        l1 = l1 * corr1 + sum1;

        __syncwarp();

        // ---- O += P @ V : 16q x 128d over warp's 32 kv ----
#pragma unroll
        for (int ks = 0; ks < 4; ++ks) {
            float2 pa0 = Ps2[(wk2 * 4 + ks) * SP2 + row0 * 4 + t];  // {a0, a2}
            float2 pa1 = Ps2[(wk2 * 4 + ks) * SP2 + row1 * 4 + t];  // {a1, a3}
            uint32_t a0 = fbits(pa0.x), a2 = fbits(pa0.y);
            uint32_t a1 = fbits(pa1.x), a3 = fbits(pa1.y);
#pragma unroll
            for (int nf = 0; nf < 16; ++nf) {
                float2 vb = Vs2[(wk2 * 4 + ks) * SV2 + (nf * 8 + g) * 4 + t];
                MMA_TF32(o[nf], a0, a1, a2, a3, fbits(vb.x), fbits(vb.y));
            }
        }
    }

    // ---- split-k merge across wk2 halves ----
    if (t == 0) {
        mlb[wk2 * 64 + row0] = m0;
        mlb[wk2 * 64 + row1] = m1;
        mlb[128 + wk2 * 64 + row0] = l0;
        mlb[128 + wk2 * 64 + row1] = l1;
    }
    __syncthreads();
    float mo0 = mlb[(1 - wk2) * 64 + row0], mo1 = mlb[(1 - wk2) * 64 + row1];
    float lo0 = mlb[128 + (1 - wk2) * 64 + row0], lo1 = mlb[128 + (1 - wk2) * 64 + row1];
    float mf0 = fmaxf(m0, mo0), mf1 = fmaxf(m1, mo1);
    float al0 = __expf(m0 - mf0), al1 = __expf(m1 - mf1);
    float ao0 = __expf(mo0 - mf0), ao1 = __expf(mo1 - mf1);
    float lf0 = l0 * al0 + lo0 * ao0;
    float lf1 = l1 * al1 + lo1 * ao1;

    if (wk2 == 1) {
#pragma unroll
        for (int nf = 0; nf < 16; ++nf) {
            stg[row0 * 68 + nf * 4 + t] = make_float2(o[nf][0] * al0, o[nf][1] * al0);
            stg[row1 * 68 + nf * 4 + t] = make_float2(o[nf][2] * al1, o[nf][3] * al1);
        }
    }
    __syncthreads();
    if (wk2 == 0) {
        float inv0 = 1.f / lf0, inv1 = 1.f / lf1;
#pragma unroll
        for (int nf = 0; nf < 16; ++nf) {
            int col = h * HD + nf * 8 + 2 * t;
            float2 s0 = stg[row0 * 68 + nf * 4 + t];
            float2 s1 = stg[row1 * 68 + nf * 4 + t];
            float2 r0v = {(o[nf][0] * al0 + s0.x) * inv0, (o[nf][1] * al0 + s0.y) * inv0};
            float2 r1v = {(o[nf][2] * al1 + s1.x) * inv1, (o[nf][3] * al1 + s1.y) * inv1};
            *(float2*)(Oout + (size_t)(qrow0 + row0) * (NH * HD) + col) = r0v;
            *(float2*)(Oout + (size_t)(qrow0 + row1) * (NH * HD) + col) = r1v;
        }
    }
}

// ---------------------------------------------------------------------------
extern "C" void kernel_launch(void* const* d_in, const int* in_sizes, int n_in,
                              void* d_out, int out_size) {
    const float* x  = (const float*)d_in[0];
    const float* wq = (const float*)d_in[1];
    const float* wk = (const float*)d_in[2];
    const float* wv = (const float*)d_in[3];
    const float* wo = (const float*)d_in[4];
    float* out = (float*)d_out;

    float *q, *k, *v, *attn;
    cudaGetSymbolAddress((void**)&q,    g_q);
    cudaGetSymbolAddress((void**)&k,    g_k);
    cudaGetSymbolAddress((void**)&v,    g_v);
    cudaGetSymbolAddress((void**)&attn, g_attn);

    const int smem_g0 = 2 * 128 * GS * 4;
    const int smem_g1 = 4 * 128 * GS * 4;
    cudaFuncSetAttribute(gemm_tf32<0>, cudaFuncAttributeMaxDynamicSharedMemorySize, smem_g0);
    cudaFuncSetAttribute(gemm_tf32<1>, cudaFuncAttributeMaxDynamicSharedMemorySize, smem_g1);
    cudaFuncSetAttribute(attn_tc2, cudaFuncAttributeMaxDynamicSharedMemorySize, ATTN2_SMEM_BYTES);

    const float scale = 0.08838834764831845f;  // 1/sqrt(128)

    gemm_tf32<0><<<dim3((NH * HD) / 128, MM / 128), 256, smem_g0>>>(x, wq, q, MM, NH * HD, DD, scale);
    gemm_tf32<0><<<dim3((NKV * HD) / 128, MM / 128), 256, smem_g0>>>(x, wk, k, MM, NKV * HD, DD, 1.f);
    gemm_tf32<0><<<dim3((NKV * HD) / 128, MM / 128), 256, smem_g0>>>(x, wv, v, MM, NKV * HD, DD, 1.f);

    attn_tc2<<<dim3(SS / 64, BB * NH), 256, ATTN2_SMEM_BYTES>>>(q, k, v, attn);

    gemm_tf32<1><<<dim3(DD / 128, MM / 128), 256, smem_g1>>>(attn, wo, out, MM, DD, DD, 1.f);
}